// round 2
// baseline (speedup 1.0000x reference)
#include <cuda_runtime.h>

// Problem constants
#define B     4
#define N     8192
#define CIN   256
#define H     8
#define D     64
#define INNER 512
#define COUT  256
#define BH    (B*H)
#define NBLK  (N/64)     // 128 row-blocks per (b,h)

// Static device scratch (allocation-free rule: __device__ globals)
__device__ float g_part[(size_t)BH * NBLK * D * D];  // 64 MB: per-block dots partials
__device__ float g_dots[BH * D * D];                 // 512 KB
__device__ float g_wqe [B * INNER * CIN];            // 2 MB:  dots-folded Wq
__device__ float g_wfin[B * COUT * CIN];             // 1 MB:  fully folded weight

// ---- packed f32x2 helpers (Blackwell) ----
__device__ __forceinline__ unsigned long long pack2(float a) {
    unsigned long long r;
    asm("mov.b64 %0, {%1, %1};" : "=l"(r) : "f"(a));
    return r;
}
__device__ __forceinline__ void fma2(unsigned long long& c,
                                     unsigned long long a,
                                     unsigned long long w) {
    asm("fma.rn.f32x2 %0, %1, %2, %0;" : "+l"(c) : "l"(a), "l"(w));
}

// ============================================================================
// K1: per (b,h,64-row tile): K/V projection (64x128x256 GEMM) + instance-norm
//     + partial dots[64,64] accumulation, written to g_part.
// Block 256 threads (tx=16, ty=16). Thread owns 4 rows x 8 cols (as 4 f32x2).
// ============================================================================
__global__ __launch_bounds__(256) void k1_proj_norm_dots(
    const float* __restrict__ ux,
    const float* __restrict__ Wk,
    const float* __restrict__ Wv)
{
    const int b = blockIdx.z, h = blockIdx.y, nb = blockIdx.x;
    const int bh = b * H + h;
    const int row0 = nb * 64;
    const int tid = threadIdx.x;
    const int tx = tid & 15, ty = tid >> 4;

    __shared__ float sbuf[64 * 130];   // aliased: [A|W] during mainloop, C after
    __shared__ float sStat[256];       // mean[128], rstd[128]
    float* sA = sbuf;                  // [32][65]  (A^T tile: [kk][row])
    float* sW = sbuf + 2080;           // [32][130] (W^T tile: [kk][col])
    float* sC = sbuf;                  // [64][130] result tile

    unsigned long long acc[4][4];
#pragma unroll
    for (int r = 0; r < 4; ++r)
#pragma unroll
        for (int j = 0; j < 4; ++j) acc[r][j] = 0ull;

    const float* uxb = ux + ((size_t)(b * N + row0)) * CIN;

    for (int kt = 0; kt < CIN; kt += 32) {
        __syncthreads();
#pragma unroll
        for (int l = 0; l < 8; ++l) {                 // A tile 64x32
            int idx = tid + l * 256;
            int r = idx >> 5, c = idx & 31;
            sA[c * 65 + r] = uxb[r * CIN + kt + c];
        }
#pragma unroll
        for (int l = 0; l < 16; ++l) {                // W tile 128x32 (Wk|Wv head h)
            int idx = tid + l * 256;
            int i = idx >> 5, c = idx & 31;
            const float* Wsrc = (i < 64) ? Wk : Wv;
            sW[c * 130 + i] = Wsrc[(h * 64 + (i & 63)) * CIN + kt + c];
        }
        __syncthreads();
#pragma unroll
        for (int kk = 0; kk < 32; ++kk) {
            const unsigned long long* wp =
                reinterpret_cast<const unsigned long long*>(&sW[kk * 130 + tx * 8]);
            unsigned long long w0 = wp[0], w1 = wp[1], w2 = wp[2], w3 = wp[3];
            const float* ap = &sA[kk * 65 + ty * 4];
#pragma unroll
            for (int r = 0; r < 4; ++r) {
                unsigned long long aa = pack2(ap[r]);
                fma2(acc[r][0], aa, w0);
                fma2(acc[r][1], aa, w1);
                fma2(acc[r][2], aa, w2);
                fma2(acc[r][3], aa, w3);
            }
        }
    }
    __syncthreads();

    // spill result tile to smem (cols 0..63 = k, 64..127 = v)
#pragma unroll
    for (int r = 0; r < 4; ++r)
#pragma unroll
        for (int j = 0; j < 4; ++j)
            *reinterpret_cast<unsigned long long*>(
                &sC[(ty * 4 + r) * 130 + tx * 8 + 2 * j]) = acc[r][j];
    __syncthreads();

    // instance-norm stats per (row, group) over 64 channels
    if (tid < 128) {
        int row = tid & 63, grp = tid >> 6;
        const float* p = &sC[row * 130 + grp * 64];
        float s = 0.f, s2 = 0.f;
#pragma unroll
        for (int d = 0; d < 64; ++d) { float x = p[d]; s += x; s2 += x * x; }
        float mean = s * (1.f / 64.f);
        float var  = s2 * (1.f / 64.f) - mean * mean;
        sStat[tid]       = mean;
        sStat[128 + tid] = rsqrtf(var + 1e-5f);
    }
    __syncthreads();

    // normalize in place
    for (int idx = tid; idx < 64 * 128; idx += 256) {
        int row = idx >> 7, col = idx & 127, grp = col >> 6;
        float m  = sStat[grp * 64 + row];
        float rs = sStat[128 + grp * 64 + row];
        sC[row * 130 + col] = (sC[row * 130 + col] - m) * rs;
    }
    __syncthreads();

    // partial dots[d,e] += sum_n k[n,d] * v[n,e] over the 64 rows
    // thread owns d = ty*4+i (4), e = tx*4 + {0..3} (2 f32x2 pairs)
    unsigned long long dacc[4][2];
#pragma unroll
    for (int i = 0; i < 4; ++i) { dacc[i][0] = 0ull; dacc[i][1] = 0ull; }

    for (int nn = 0; nn < 64; ++nn) {
        const float* kp = &sC[nn * 130 + ty * 4];
        const unsigned long long* vp =
            reinterpret_cast<const unsigned long long*>(&sC[nn * 130 + 64 + tx * 4]);
        unsigned long long v0 = vp[0], v1 = vp[1];
#pragma unroll
        for (int i = 0; i < 4; ++i) {
            unsigned long long kk2 = pack2(kp[i]);
            fma2(dacc[i][0], kk2, v0);
            fma2(dacc[i][1], kk2, v1);
        }
    }

    float* pp = g_part + ((size_t)(bh * NBLK + nb)) * 4096;
#pragma unroll
    for (int i = 0; i < 4; ++i) {
        int d_ = ty * 4 + i;
        *reinterpret_cast<unsigned long long*>(&pp[d_ * 64 + tx * 4])     = dacc[i][0];
        *reinterpret_cast<unsigned long long*>(&pp[d_ * 64 + tx * 4 + 2]) = dacc[i][1];
    }
}

// ============================================================================
// K2: reduce 128 partials -> g_dots
// ============================================================================
__global__ __launch_bounds__(256) void k2_reduce()
{
    int gid = blockIdx.x * 256 + threadIdx.x;       // 131072 outputs
    int bh = gid >> 12, de = gid & 4095;
    const float* p = g_part + (size_t)bh * NBLK * 4096 + de;
    float s = 0.f;
#pragma unroll 8
    for (int q = 0; q < NBLK; ++q) s += p[(size_t)q * 4096];
    g_dots[gid] = s;
}

// ============================================================================
// K3a: Wq_eff[b, h*64+e, c] = (1/N) * sum_d dots[b,h,d,e] * Wq[h*64+d, c]
// ============================================================================
__global__ __launch_bounds__(256) void k3_wqe(const float* __restrict__ Wq)
{
    const int h = blockIdx.x, b = blockIdx.y;
    const int bh = b * H + h;
    __shared__ float sd[4096];
    for (int idx = threadIdx.x; idx < 4096; idx += 256)
        sd[idx] = g_dots[bh * 4096 + idx];
    __syncthreads();

    const int c = threadIdx.x;
    float acc[64];
#pragma unroll
    for (int e = 0; e < 64; ++e) acc[e] = 0.f;
    for (int d = 0; d < 64; ++d) {
        float w = Wq[(h * 64 + d) * CIN + c];
#pragma unroll
        for (int e = 0; e < 64; ++e) acc[e] += sd[d * 64 + e] * w;
    }
    const float invN = 1.0f / (float)N;
    for (int e = 0; e < 64; ++e)
        g_wqe[((size_t)b * INNER + h * 64 + e) * CIN + c] = acc[e] * invN;
}

// ============================================================================
// K3b: Wfinal[b,o,c] = sum_e Wo[o,e] * Wq_eff[b,e,c]
// ============================================================================
__global__ __launch_bounds__(256) void k3_wfin(const float* __restrict__ Wo)
{
    const int o0 = blockIdx.x * 16, b = blockIdx.y;
    __shared__ float sWo[16 * 512];
    for (int idx = threadIdx.x; idx < 8192; idx += 256)
        sWo[idx] = Wo[(o0 + (idx >> 9)) * INNER + (idx & 511)];
    __syncthreads();

    const int c = threadIdx.x;
    float acc[16];
#pragma unroll
    for (int i = 0; i < 16; ++i) acc[i] = 0.f;
    for (int e = 0; e < 512; ++e) {
        float wq = g_wqe[((size_t)b * INNER + e) * CIN + c];
#pragma unroll
        for (int i = 0; i < 16; ++i) acc[i] += sWo[i * 512 + e] * wq;
    }
    for (int i = 0; i < 16; ++i)
        g_wfin[((size_t)b * COUT + o0 + i) * CIN + c] = acc[i];
}

// ============================================================================
// K4: out[b,n,o] = u_x[b,n,:] . Wfinal[b,o,:] + bo[o]
// Same tiling as K1 (64 rows x 128 cols, K-tile 32).
// ============================================================================
__global__ __launch_bounds__(256) void k4_out(
    const float* __restrict__ ux,
    const float* __restrict__ bo,
    float* __restrict__ out)
{
    const int b = blockIdx.z;
    const int o0 = blockIdx.y * 128;
    const int row0 = blockIdx.x * 64;
    const int tid = threadIdx.x;
    const int tx = tid & 15, ty = tid >> 4;

    __shared__ float sbuf[2080 + 4160];
    float* sA = sbuf;          // [32][65]
    float* sW = sbuf + 2080;   // [32][130]

    unsigned long long acc[4][4];
#pragma unroll
    for (int r = 0; r < 4; ++r)
#pragma unroll
        for (int j = 0; j < 4; ++j) acc[r][j] = 0ull;

    const float* uxb = ux + ((size_t)(b * N + row0)) * CIN;
    const float* Wb  = g_wfin + (size_t)b * COUT * CIN + (size_t)o0 * CIN;

    for (int kt = 0; kt < CIN; kt += 32) {
        __syncthreads();
#pragma unroll
        for (int l = 0; l < 8; ++l) {
            int idx = tid + l * 256;
            int r = idx >> 5, c = idx & 31;
            sA[c * 65 + r] = uxb[r * CIN + kt + c];
        }
#pragma unroll
        for (int l = 0; l < 16; ++l) {
            int idx = tid + l * 256;
            int i = idx >> 5, c = idx & 31;
            sW[c * 130 + i] = Wb[i * CIN + kt + c];
        }
        __syncthreads();
#pragma unroll
        for (int kk = 0; kk < 32; ++kk) {
            const unsigned long long* wp =
                reinterpret_cast<const unsigned long long*>(&sW[kk * 130 + tx * 8]);
            unsigned long long w0 = wp[0], w1 = wp[1], w2 = wp[2], w3 = wp[3];
            const float* ap = &sA[kk * 65 + ty * 4];
#pragma unroll
            for (int r = 0; r < 4; ++r) {
                unsigned long long aa = pack2(ap[r]);
                fma2(acc[r][0], aa, w0);
                fma2(acc[r][1], aa, w1);
                fma2(acc[r][2], aa, w2);
                fma2(acc[r][3], aa, w3);
            }
        }
    }

    // epilogue: + bias, store
#pragma unroll
    for (int r = 0; r < 4; ++r) {
        float* orow = out + ((size_t)(b * N) + row0 + ty * 4 + r) * COUT + o0 + tx * 8;
#pragma unroll
        for (int j = 0; j < 4; ++j) {
            float2 v = *reinterpret_cast<float2*>(&acc[r][j]);
            float2 bb = *reinterpret_cast<const float2*>(&bo[o0 + tx * 8 + 2 * j]);
            v.x += bb.x; v.y += bb.y;
            *reinterpret_cast<float2*>(&orow[2 * j]) = v;
        }
    }
}

// ============================================================================
extern "C" void kernel_launch(void* const* d_in, const int* in_sizes, int n_in,
                              void* d_out, int out_size)
{
    const float* ux = (const float*)d_in[0];
    // d_in[1] = pos_x (unused by the reference computation)
    const float* Wq = (const float*)d_in[2];
    const float* Wk = (const float*)d_in[3];
    const float* Wv = (const float*)d_in[4];
    const float* Wo = (const float*)d_in[5];
    const float* bo = (const float*)d_in[6];
    float* out = (float*)d_out;

    k1_proj_norm_dots<<<dim3(NBLK, H, B), 256>>>(ux, Wk, Wv);
    k2_reduce<<<512, 256>>>();
    k3_wqe<<<dim3(H, B), 256>>>(Wq);
    k3_wfin<<<dim3(COUT / 16, B), 256>>>(Wo);
    k4_out<<<dim3(NBLK, 2, B), 256>>>(ux, bo, out);
}

// round 3
// speedup vs baseline: 1.7767x; 1.7767x over previous
#include <cuda_runtime.h>

// Problem constants
#define B     4
#define N     8192
#define CIN   256
#define H     8
#define D     64
#define INNER 512
#define COUT  256
#define BH    (B*H)
#define NBLK  (N/64)     // 128 row-blocks per (b,h)

// Static device scratch (allocation-free rule: __device__ globals)
__device__ float g_part[(size_t)BH * NBLK * D * D];  // 64 MB: per-block dots partials
__device__ float g_dots[BH * D * D];                 // 512 KB
__device__ float g_wqe [B * INNER * CIN];            // 2 MB:  dots-folded Wq
__device__ float g_wfin[B * COUT * CIN];             // 1 MB:  fully folded weight

// ---- packed f32x2 helpers (Blackwell) ----
__device__ __forceinline__ unsigned long long pack2(float a) {
    unsigned long long r;
    asm("mov.b64 %0, {%1, %1};" : "=l"(r) : "f"(a));
    return r;
}
__device__ __forceinline__ void fma2(unsigned long long& c,
                                     unsigned long long a,
                                     unsigned long long w) {
    asm("fma.rn.f32x2 %0, %1, %2, %0;" : "+l"(c) : "l"(a), "l"(w));
}

// ============================================================================
// K1: per (b,h,64-row tile): K/V projection (64x128x256 GEMM) + instance-norm
//     + partial dots[64,64] accumulation, written to g_part.
// Block 256 threads (tx=16, ty=16). Thread owns 4 rows x 8 cols.
// Column ownership is INTERLEAVED: cols {2tx, 2tx+1} + 32*j, j=0..3
// -> all mainloop LDS.64 are bank-conflict-free (stride-2-word across 16 tx).
// ============================================================================
__global__ __launch_bounds__(256) void k1_proj_norm_dots(
    const float* __restrict__ ux,
    const float* __restrict__ Wk,
    const float* __restrict__ Wv)
{
    const int b = blockIdx.z, h = blockIdx.y, nb = blockIdx.x;
    const int bh = b * H + h;
    const int row0 = nb * 64;
    const int tid = threadIdx.x;
    const int tx = tid & 15, ty = tid >> 4;

    __shared__ float sbuf[64 * 130];   // aliased: [A|W] during mainloop, C after
    __shared__ float sStat[256];       // mean[128], rstd[128]
    float* sA = sbuf;                  // [32][65]  (A^T tile: [kk][row])
    float* sW = sbuf + 2080;           // [32][130] (W^T tile: [kk][col])
    float* sC = sbuf;                  // [64][130] result tile

    unsigned long long acc[4][4];
#pragma unroll
    for (int r = 0; r < 4; ++r)
#pragma unroll
        for (int j = 0; j < 4; ++j) acc[r][j] = 0ull;

    const float* uxb = ux + ((size_t)(b * N + row0)) * CIN;

    for (int kt = 0; kt < CIN; kt += 32) {
        __syncthreads();
#pragma unroll
        for (int l = 0; l < 8; ++l) {                 // A tile 64x32
            int idx = tid + l * 256;
            int r = idx >> 5, c = idx & 31;
            sA[c * 65 + r] = uxb[r * CIN + kt + c];
        }
#pragma unroll
        for (int l = 0; l < 16; ++l) {                // W tile 128x32 (Wk|Wv head h)
            int idx = tid + l * 256;
            int i = idx >> 5, c = idx & 31;
            const float* Wsrc = (i < 64) ? Wk : Wv;
            sW[c * 130 + i] = Wsrc[(h * 64 + (i & 63)) * CIN + kt + c];
        }
        __syncthreads();
#pragma unroll
        for (int kk = 0; kk < 32; ++kk) {
            const float* wrow = &sW[kk * 130 + 2 * tx];
            unsigned long long w0 = *reinterpret_cast<const unsigned long long*>(wrow);
            unsigned long long w1 = *reinterpret_cast<const unsigned long long*>(wrow + 32);
            unsigned long long w2 = *reinterpret_cast<const unsigned long long*>(wrow + 64);
            unsigned long long w3 = *reinterpret_cast<const unsigned long long*>(wrow + 96);
            const float* ap = &sA[kk * 65 + ty * 4];
#pragma unroll
            for (int r = 0; r < 4; ++r) {
                unsigned long long aa = pack2(ap[r]);
                fma2(acc[r][0], aa, w0);
                fma2(acc[r][1], aa, w1);
                fma2(acc[r][2], aa, w2);
                fma2(acc[r][3], aa, w3);
            }
        }
    }
    __syncthreads();

    // spill result tile to smem (cols 0..63 = k, 64..127 = v); conflict-free stores
#pragma unroll
    for (int r = 0; r < 4; ++r)
#pragma unroll
        for (int j = 0; j < 4; ++j)
            *reinterpret_cast<unsigned long long*>(
                &sC[(ty * 4 + r) * 130 + 2 * tx + 32 * j]) = acc[r][j];
    __syncthreads();

    // instance-norm stats per (row, group) over 64 channels
    if (tid < 128) {
        int row = tid & 63, grp = tid >> 6;
        const float* p = &sC[row * 130 + grp * 64];
        float s = 0.f, s2 = 0.f;
#pragma unroll
        for (int d = 0; d < 64; ++d) { float x = p[d]; s += x; s2 += x * x; }
        float mean = s * (1.f / 64.f);
        float var  = s2 * (1.f / 64.f) - mean * mean;
        sStat[tid]       = mean;
        sStat[128 + tid] = rsqrtf(var + 1e-5f);
    }
    __syncthreads();

    // normalize in place (stride-1 across threads: conflict-free)
    for (int idx = tid; idx < 64 * 128; idx += 256) {
        int row = idx >> 7, col = idx & 127, grp = col >> 6;
        float m  = sStat[grp * 64 + row];
        float rs = sStat[128 + grp * 64 + row];
        sC[row * 130 + col] = (sC[row * 130 + col] - m) * rs;
    }
    __syncthreads();

    // partial dots[d,e] += sum_n k[n,d] * v[n,e] over the 64 rows
    // thread owns d = ty*4+i (4), e in {2tx,2tx+1} and {2tx+32,2tx+33}
    unsigned long long dacc[4][2];
#pragma unroll
    for (int i = 0; i < 4; ++i) { dacc[i][0] = 0ull; dacc[i][1] = 0ull; }

    for (int nn = 0; nn < 64; ++nn) {
        const float* kp = &sC[nn * 130 + ty * 4];
        const float* vrow = &sC[nn * 130 + 64 + 2 * tx];
        unsigned long long v0 = *reinterpret_cast<const unsigned long long*>(vrow);
        unsigned long long v1 = *reinterpret_cast<const unsigned long long*>(vrow + 32);
#pragma unroll
        for (int i = 0; i < 4; ++i) {
            unsigned long long kk2 = pack2(kp[i]);
            fma2(dacc[i][0], kk2, v0);
            fma2(dacc[i][1], kk2, v1);
        }
    }

    float* pp = g_part + ((size_t)(bh * NBLK + nb)) * 4096;
#pragma unroll
    for (int i = 0; i < 4; ++i) {
        int d_ = ty * 4 + i;
        *reinterpret_cast<unsigned long long*>(&pp[d_ * 64 + 2 * tx])      = dacc[i][0];
        *reinterpret_cast<unsigned long long*>(&pp[d_ * 64 + 2 * tx + 32]) = dacc[i][1];
    }
}

// ============================================================================
// K2: reduce 128 partials -> g_dots (vectorized float4)
// 131072 outputs / 4 per thread = 32768 threads = 128 blocks
// ============================================================================
__global__ __launch_bounds__(256) void k2_reduce()
{
    int gid = blockIdx.x * 256 + threadIdx.x;        // 32768 float4 outputs
    int bh = gid >> 10, de4 = gid & 1023;
    const float4* p = reinterpret_cast<const float4*>(
        g_part + (size_t)bh * NBLK * 4096) + de4;
    float4 s = make_float4(0.f, 0.f, 0.f, 0.f);
#pragma unroll 8
    for (int q = 0; q < NBLK; ++q) {
        float4 v = p[(size_t)q * 1024];
        s.x += v.x; s.y += v.y; s.z += v.z; s.w += v.w;
    }
    reinterpret_cast<float4*>(g_dots)[gid] = s;
}

// ============================================================================
// K3a: Wq_eff[b, h*64+e, c] = (1/N) * sum_d dots[b,h,d,e] * Wq[h*64+d, c]
// grid (4 ctiles, H, B) = 128 blocks; thread owns 1 col, 16 e's.
// ============================================================================
__global__ __launch_bounds__(256) void k3_wqe(const float* __restrict__ Wq)
{
    const int c0 = blockIdx.x * 64, h = blockIdx.y, b = blockIdx.z;
    const int bh = b * H + h;
    const int tid = threadIdx.x;
    __shared__ float sd[4096];
    for (int idx = tid; idx < 4096; idx += 256)
        sd[idx] = g_dots[bh * 4096 + idx];
    __syncthreads();

    const int c = c0 + (tid & 63);
    const int e0 = (tid >> 6) * 16;
    float acc[16];
#pragma unroll
    for (int e = 0; e < 16; ++e) acc[e] = 0.f;
    for (int d = 0; d < 64; ++d) {
        float w = Wq[(h * 64 + d) * CIN + c];
        const float* sdr = &sd[d * 64 + e0];
#pragma unroll
        for (int e = 0; e < 16; ++e) acc[e] += sdr[e] * w;
    }
    const float invN = 1.0f / (float)N;
#pragma unroll
    for (int e = 0; e < 16; ++e)
        g_wqe[((size_t)b * INNER + h * 64 + e0 + e) * CIN + c] = acc[e] * invN;
}

// ============================================================================
// K3b: Wfinal[b,o,c] = sum_e Wo[o,e] * Wq_eff[b,e,c]
// grid (8 otiles, 8 ctiles, B) = 256 blocks; 32x32 tile, K=512 in 32-chunks.
// Thread owns c = c0+(tid&31), o's = o0+(tid>>5)*4 + {0..3}.
// ============================================================================
__global__ __launch_bounds__(256) void k3_wfin(const float* __restrict__ Wo)
{
    const int o0 = blockIdx.x * 32, c0 = blockIdx.y * 32, b = blockIdx.z;
    const int tid = threadIdx.x;
    __shared__ float sO[32 * 36];   // sO[e][o], padded (36 words: 16B-aligned rows)
    __shared__ float sQ[32 * 33];   // sQ[e][c]

    const int cl = tid & 31;
    const int ol = (tid >> 5) * 4;
    float acc[4] = {0.f, 0.f, 0.f, 0.f};

    for (int e0 = 0; e0 < INNER; e0 += 32) {
        __syncthreads();
        {
            int i = tid >> 5;           // 8 rows per pass, 4 passes
            int j = tid & 31;
#pragma unroll
            for (int p = 0; p < 4; ++p) {
                int r = i + p * 8;
                sO[j * 36 + r] = Wo[(o0 + r) * INNER + e0 + j];        // transpose
                sQ[r * 33 + j] = g_wqe[((size_t)b * INNER + e0 + r) * CIN + c0 + j];
            }
        }
        __syncthreads();
#pragma unroll
        for (int ee = 0; ee < 32; ++ee) {
            float q = sQ[ee * 33 + cl];
            const float4 wo4 = *reinterpret_cast<const float4*>(&sO[ee * 36 + ol]);
            acc[0] += wo4.x * q;
            acc[1] += wo4.y * q;
            acc[2] += wo4.z * q;
            acc[3] += wo4.w * q;
        }
    }
#pragma unroll
    for (int j = 0; j < 4; ++j)
        g_wfin[((size_t)b * COUT + o0 + ol + j) * CIN + c0 + cl] = acc[j];
}

// ============================================================================
// K4: out[b,n,o] = u_x[b,n,:] . Wfinal[b,o,:] + bo[o]
// Same tiling as K1 (64 rows x 128 cols, K-tile 32), interleaved columns.
// ============================================================================
__global__ __launch_bounds__(256) void k4_out(
    const float* __restrict__ ux,
    const float* __restrict__ bo,
    float* __restrict__ out)
{
    const int b = blockIdx.z;
    const int o0 = blockIdx.y * 128;
    const int row0 = blockIdx.x * 64;
    const int tid = threadIdx.x;
    const int tx = tid & 15, ty = tid >> 4;

    __shared__ float sbuf[2080 + 4160];
    float* sA = sbuf;          // [32][65]
    float* sW = sbuf + 2080;   // [32][130]

    unsigned long long acc[4][4];
#pragma unroll
    for (int r = 0; r < 4; ++r)
#pragma unroll
        for (int j = 0; j < 4; ++j) acc[r][j] = 0ull;

    const float* uxb = ux + ((size_t)(b * N + row0)) * CIN;
    const float* Wb  = g_wfin + (size_t)b * COUT * CIN + (size_t)o0 * CIN;

    for (int kt = 0; kt < CIN; kt += 32) {
        __syncthreads();
#pragma unroll
        for (int l = 0; l < 8; ++l) {
            int idx = tid + l * 256;
            int r = idx >> 5, c = idx & 31;
            sA[c * 65 + r] = uxb[r * CIN + kt + c];
        }
#pragma unroll
        for (int l = 0; l < 16; ++l) {
            int idx = tid + l * 256;
            int i = idx >> 5, c = idx & 31;
            sW[c * 130 + i] = Wb[i * CIN + kt + c];
        }
        __syncthreads();
#pragma unroll
        for (int kk = 0; kk < 32; ++kk) {
            const float* wrow = &sW[kk * 130 + 2 * tx];
            unsigned long long w0 = *reinterpret_cast<const unsigned long long*>(wrow);
            unsigned long long w1 = *reinterpret_cast<const unsigned long long*>(wrow + 32);
            unsigned long long w2 = *reinterpret_cast<const unsigned long long*>(wrow + 64);
            unsigned long long w3 = *reinterpret_cast<const unsigned long long*>(wrow + 96);
            const float* ap = &sA[kk * 65 + ty * 4];
#pragma unroll
            for (int r = 0; r < 4; ++r) {
                unsigned long long aa = pack2(ap[r]);
                fma2(acc[r][0], aa, w0);
                fma2(acc[r][1], aa, w1);
                fma2(acc[r][2], aa, w2);
                fma2(acc[r][3], aa, w3);
            }
        }
    }

    // epilogue: + bias, store (interleaved cols: o0 + 2tx + 32j)
#pragma unroll
    for (int r = 0; r < 4; ++r) {
        float* orow = out + ((size_t)(b * N) + row0 + ty * 4 + r) * COUT + o0;
#pragma unroll
        for (int j = 0; j < 4; ++j) {
            int col = 2 * tx + 32 * j;
            float2 v = *reinterpret_cast<float2*>(&acc[r][j]);
            float2 bb = *reinterpret_cast<const float2*>(&bo[o0 + col]);
            v.x += bb.x; v.y += bb.y;
            *reinterpret_cast<float2*>(&orow[col]) = v;
        }
    }
}

// ============================================================================
extern "C" void kernel_launch(void* const* d_in, const int* in_sizes, int n_in,
                              void* d_out, int out_size)
{
    const float* ux = (const float*)d_in[0];
    // d_in[1] = pos_x (unused by the reference computation)
    const float* Wq = (const float*)d_in[2];
    const float* Wk = (const float*)d_in[3];
    const float* Wv = (const float*)d_in[4];
    const float* Wo = (const float*)d_in[5];
    const float* bo = (const float*)d_in[6];
    float* out = (float*)d_out;

    k1_proj_norm_dots<<<dim3(NBLK, H, B), 256>>>(ux, Wk, Wv);
    k2_reduce<<<128, 256>>>();
    k3_wqe<<<dim3(4, H, B), 256>>>(Wq);
    k3_wfin<<<dim3(8, 8, B), 256>>>(Wo);
    k4_out<<<dim3(NBLK, 2, B), 256>>>(ux, bo, out);
}